// round 1
// baseline (speedup 1.0000x reference)
#include <cuda_runtime.h>
#include <cuda_bf16.h>
#include <cstddef>

// LIF activation over time axis.
// x: [B=64, T=500, C=1024] fp32; w_input, w_leak: scalars (device).
// out: spikes [B, T, C] fp32 (0.0 / 1.0).
// One thread per (b, c) lane; sequential over T with unroll-10 load batching
// so each warp keeps 10 x 128B coalesced loads in flight (hides DRAM latency).

#define LIF_B 64
#define LIF_T 500
#define LIF_C 1024
#define LIF_UNROLL 10

__global__ __launch_bounds__(256) void lif_kernel(
    const float* __restrict__ x,
    const float* __restrict__ w_input_p,
    const float* __restrict__ w_leak_p,
    float* __restrict__ out)
{
    const int tid = blockIdx.x * blockDim.x + threadIdx.x;  // 0 .. B*C-1
    const float wi   = *w_input_p;
    const float keep = 1.0f - *w_leak_p;

    const int b = tid >> 10;        // / C
    const int c = tid & (LIF_C - 1);

    const size_t base = (size_t)b * LIF_T * LIF_C + c;
    const float* xp = x + base;
    float* op = out + base;

    float Vm = 0.0f;

    #pragma unroll 1
    for (int t0 = 0; t0 < LIF_T; t0 += LIF_UNROLL) {
        // Front-batch independent loads (raises per-warp MLP to 10).
        float xv[LIF_UNROLL];
        #pragma unroll
        for (int i = 0; i < LIF_UNROLL; i++)
            xv[i] = xp[(size_t)(t0 + i) * LIF_C];

        // Sequential recurrence on registers.
        float sp[LIF_UNROLL];
        #pragma unroll
        for (int i = 0; i < LIF_UNROLL; i++) {
            // forget = step(1 - Vm) : reset if Vm crossed threshold
            const float forget = ((1.0f - Vm) > 0.0f) ? 1.0f : 0.0f;
            const float v = wi * xv[i] + keep * Vm * forget;
            Vm = fmaxf(v, 0.0f);
            sp[i] = ((Vm - 1.0f) > 0.0f) ? 1.0f : 0.0f;
        }

        #pragma unroll
        for (int i = 0; i < LIF_UNROLL; i++)
            op[(size_t)(t0 + i) * LIF_C] = sp[i];
    }
}

extern "C" void kernel_launch(void* const* d_in, const int* in_sizes, int n_in,
                              void* d_out, int out_size) {
    const float* x        = (const float*)d_in[0];
    const float* w_input  = (const float*)d_in[1];
    const float* w_leak   = (const float*)d_in[2];
    float* out            = (float*)d_out;

    const int lanes = LIF_B * LIF_C;  // 65536
    lif_kernel<<<lanes / 256, 256>>>(x, w_input, w_leak, out);
}